// round 4
// baseline (speedup 1.0000x reference)
#include <cuda_runtime.h>

#define BATCHN   131072
#define SDIM     137
#define W0COLS   139
#define HID      256
#define AHD      128
#define NBLK     4
#define ROWS     64
#define NTHREADS 256
#define SSTRIDE  144   // padded state row stride (16B aligned)

#define SMEM_FLOATS (2*ROWS*HID + ROWS*SSTRIDE)
#define SMEM_BYTES  (SMEM_FLOATS * 4)

// ---- small precomputed scratch (device globals: no allocation allowed) ----
__device__ float g_b0p[HID];        // b0 + sin*W0[:,137] + cos*W0[:,138]
__device__ float g_Mta[AHD*AHD];    // ta_out_w @ Wv_ta
__device__ float g_cta[AHD];        // ta_out_w @ bv_ta + ta_out_b
__device__ float g_Mlm[64];         // lm_out_w @ Wv_lm  (8x8)
__device__ float g_clm[8];

__global__ void prep1(const float* __restrict__ t, const float* __restrict__ W0,
                      const float* __restrict__ b0,
                      const float* __restrict__ lm_in_w, const float* __restrict__ lm_in_b,
                      const float* __restrict__ lm_out_w, const float* __restrict__ lm_out_b,
                      const float* __restrict__ ta_in_b,
                      const float* __restrict__ ta_out_w, const float* __restrict__ ta_out_b) {
    int tid = threadIdx.x;
    float ang = t[0] * (2.0f * 3.14159265358979323846f / 24.0f);
    float sv = sinf(ang), cv = cosf(ang);
    if (tid < HID)
        g_b0p[tid] = b0[tid] + sv * W0[tid*W0COLS + 137] + cv * W0[tid*W0COLS + 138];
    if (tid < 64) {
        int i = tid >> 3, j = tid & 7;
        float a = 0.f;
        #pragma unroll
        for (int k = 0; k < 8; k++) a += lm_out_w[i*8+k] * lm_in_w[(16+k)*8 + j];
        g_Mlm[tid] = a;
    }
    if (tid < 8) {
        float a = lm_out_b[tid];
        #pragma unroll
        for (int k = 0; k < 8; k++) a += lm_out_w[tid*8+k] * lm_in_b[16+k];
        g_clm[tid] = a;
    }
    if (tid < AHD) {
        float a = ta_out_b[tid];
        for (int k = 0; k < AHD; k++) a += ta_out_w[tid*AHD+k] * ta_in_b[2*AHD+k];
        g_cta[tid] = a;
    }
}

__global__ void prep2(const float* __restrict__ ta_in_w,
                      const float* __restrict__ ta_out_w) {
    int idx = blockIdx.x * blockDim.x + threadIdx.x;  // 64*256 = 16384 = 128*128
    int i = idx >> 7, j = idx & 127;
    float a = 0.f;
    for (int k = 0; k < AHD; k++)
        a += ta_out_w[i*AHD + k] * ta_in_w[(2*AHD + k)*AHD + j];
    g_Mta[idx] = a;
}

// 64x256 tile GEMM step: acc[rr][j] += sum_k src[rbase+rr][k] * W[tx+32j][k]
__device__ __forceinline__ void gemm_tile(const float* __restrict__ src, int srcStride,
                                          const float* __restrict__ W,
                                          int rbase, int tx, float acc[8][8]) {
    #pragma unroll 1
    for (int k = 0; k < HID; k += 4) {
        float4 hv[8];
        #pragma unroll
        for (int rr = 0; rr < 8; rr++)
            hv[rr] = *reinterpret_cast<const float4*>(&src[(rbase+rr)*srcStride + k]);
        float4 wv[8];
        #pragma unroll
        for (int j = 0; j < 8; j++)
            wv[j] = *reinterpret_cast<const float4*>(&W[(tx + 32*j)*HID + k]);
        #pragma unroll
        for (int j = 0; j < 8; j++) {
            #pragma unroll
            for (int rr = 0; rr < 8; rr++) {
                acc[rr][j] = fmaf(hv[rr].x, wv[j].x, acc[rr][j]);
                acc[rr][j] = fmaf(hv[rr].y, wv[j].y, acc[rr][j]);
                acc[rr][j] = fmaf(hv[rr].z, wv[j].z, acc[rr][j]);
                acc[rr][j] = fmaf(hv[rr].w, wv[j].w, acc[rr][j]);
            }
        }
    }
}

extern "C" __global__ void __launch_bounds__(NTHREADS, 1)
ode_main(const float* __restrict__ state,
         const float* __restrict__ W0,
         const float* __restrict__ blkW1, const float* __restrict__ blkb1,
         const float* __restrict__ blkW2, const float* __restrict__ blkb2,
         const float* __restrict__ Wout, const float* __restrict__ bout,
         float* __restrict__ out) {
    extern __shared__ float smem[];
    float* s_h = smem;                  // [ROWS][HID]
    float* s_t = smem + ROWS*HID;       // [ROWS][HID]
    float* s_s = smem + 2*ROWS*HID;     // [ROWS][SSTRIDE] (state tile)

    const int tid = threadIdx.x;
    const int tx = tid & 31;
    const int ty = tid >> 5;
    const int rbase = ty * 8;
    const int row0 = blockIdx.x * ROWS;

    // load state tile (coalesced)
    for (int i = tid; i < ROWS*SDIM; i += NTHREADS) {
        int r = i / SDIM;
        int k = i - r*SDIM;
        s_s[r*SSTRIDE + k] = state[(size_t)(row0 + r)*SDIM + k];
    }
    __syncthreads();

    float acc[8][8];

    // ---- layer 0: h = relu(state @ W0[:, :137]^T + b0p), K = 137 ----
    #pragma unroll
    for (int rr = 0; rr < 8; rr++)
        #pragma unroll
        for (int j = 0; j < 8; j++) acc[rr][j] = 0.f;

    #pragma unroll 1
    for (int k = 0; k < SDIM; k++) {
        float hv[8];
        #pragma unroll
        for (int rr = 0; rr < 8; rr++) hv[rr] = s_s[(rbase+rr)*SSTRIDE + k];
        float wv[8];
        #pragma unroll
        for (int j = 0; j < 8; j++) wv[j] = W0[(tx + 32*j)*W0COLS + k];
        #pragma unroll
        for (int j = 0; j < 8; j++)
            #pragma unroll
            for (int rr = 0; rr < 8; rr++)
                acc[rr][j] = fmaf(hv[rr], wv[j], acc[rr][j]);
    }
    #pragma unroll
    for (int j = 0; j < 8; j++) {
        int c = tx + 32*j;
        float b = g_b0p[c];
        #pragma unroll
        for (int rr = 0; rr < 8; rr++)
            s_h[(rbase+rr)*HID + c] = fmaxf(acc[rr][j] + b, 0.f);
    }
    __syncthreads();

    // ---- 4 residual blocks ----
    #pragma unroll 1
    for (int blk = 0; blk < NBLK; blk++) {
        const float* W1 = blkW1 + blk*HID*HID;
        const float* b1 = blkb1 + blk*HID;
        #pragma unroll
        for (int rr = 0; rr < 8; rr++)
            #pragma unroll
            for (int j = 0; j < 8; j++) acc[rr][j] = 0.f;
        gemm_tile(s_h, HID, W1, rbase, tx, acc);
        #pragma unroll
        for (int j = 0; j < 8; j++) {
            int c = tx + 32*j;
            float b = b1[c];
            #pragma unroll
            for (int rr = 0; rr < 8; rr++)
                s_t[(rbase+rr)*HID + c] = tanhf(acc[rr][j] + b);
        }
        __syncthreads();

        const float* W2 = blkW2 + blk*HID*HID;
        const float* b2 = blkb2 + blk*HID;
        #pragma unroll
        for (int rr = 0; rr < 8; rr++)
            #pragma unroll
            for (int j = 0; j < 8; j++) acc[rr][j] = 0.f;
        gemm_tile(s_t, HID, W2, rbase, tx, acc);
        // safe: all reads of s_h (pass A) completed before the sync above;
        // each thread writes only its own s_h elements here.
        #pragma unroll
        for (int j = 0; j < 8; j++) {
            int c = tx + 32*j;
            float b = b2[c];
            #pragma unroll
            for (int rr = 0; rr < 8; rr++) {
                float hold = s_h[(rbase+rr)*HID + c];
                s_h[(rbase+rr)*HID + c] = tanhf(hold + acc[rr][j] + b);
            }
        }
        __syncthreads();
    }

    // ---- output projection (cols 0..136) + delta path ----
    float accc[8][4];
    float acc5[8];
    float accd[8][4];
    #pragma unroll
    for (int rr = 0; rr < 8; rr++) {
        acc5[rr] = 0.f;
        #pragma unroll
        for (int j = 0; j < 4; j++) { accc[rr][j] = 0.f; accd[rr][j] = 0.f; }
    }
    const bool has5 = (tx < 9);
    const int c5 = tx + 128;

    #pragma unroll 1
    for (int k = 0; k < HID; k += 4) {
        float4 hv[8];
        #pragma unroll
        for (int rr = 0; rr < 8; rr++)
            hv[rr] = *reinterpret_cast<const float4*>(&s_h[(rbase+rr)*HID + k]);
        float4 wv[4];
        #pragma unroll
        for (int j = 0; j < 4; j++)
            wv[j] = *reinterpret_cast<const float4*>(&Wout[(tx + 32*j)*HID + k]);
        float4 w5 = make_float4(0.f, 0.f, 0.f, 0.f);
        if (has5) w5 = *reinterpret_cast<const float4*>(&Wout[c5*HID + k]);
        #pragma unroll
        for (int j = 0; j < 4; j++) {
            #pragma unroll
            for (int rr = 0; rr < 8; rr++) {
                accc[rr][j] = fmaf(hv[rr].x, wv[j].x, accc[rr][j]);
                accc[rr][j] = fmaf(hv[rr].y, wv[j].y, accc[rr][j]);
                accc[rr][j] = fmaf(hv[rr].z, wv[j].z, accc[rr][j]);
                accc[rr][j] = fmaf(hv[rr].w, wv[j].w, accc[rr][j]);
            }
        }
        #pragma unroll
        for (int rr = 0; rr < 8; rr++) {
            acc5[rr] = fmaf(hv[rr].x, w5.x, acc5[rr]);
            acc5[rr] = fmaf(hv[rr].y, w5.y, acc5[rr]);
            acc5[rr] = fmaf(hv[rr].z, w5.z, acc5[rr]);
            acc5[rr] = fmaf(hv[rr].w, w5.w, acc5[rr]);
        }
    }

    // delta_h GEMM: hs @ M_ta^T, K = 128, cols 0..127 (= tx + 32j, j<4)
    #pragma unroll 1
    for (int k = 0; k < AHD; k += 4) {
        float4 sv[8];
        #pragma unroll
        for (int rr = 0; rr < 8; rr++)
            sv[rr] = *reinterpret_cast<const float4*>(&s_s[(rbase+rr)*SSTRIDE + k]);
        float4 mv[4];
        #pragma unroll
        for (int j = 0; j < 4; j++)
            mv[j] = *reinterpret_cast<const float4*>(&g_Mta[(tx + 32*j)*AHD + k]);
        #pragma unroll
        for (int j = 0; j < 4; j++) {
            #pragma unroll
            for (int rr = 0; rr < 8; rr++) {
                accd[rr][j] = fmaf(sv[rr].x, mv[j].x, accd[rr][j]);
                accd[rr][j] = fmaf(sv[rr].y, mv[j].y, accd[rr][j]);
                accd[rr][j] = fmaf(sv[rr].z, mv[j].z, accd[rr][j]);
                accd[rr][j] = fmaf(sv[rr].w, mv[j].w, accd[rr][j]);
            }
        }
    }

    // ---- write outputs ----
    #pragma unroll
    for (int j = 0; j < 4; j++) {
        int c = tx + 32*j;
        float bo = bout[c];
        float ct = g_cta[c];
        #pragma unroll
        for (int rr = 0; rr < 8; rr++) {
            int r = rbase + rr;
            float core = accc[rr][j] + bo;
            float d = accd[rr][j] + ct - s_s[r*SSTRIDE + c];
            out[(size_t)(row0 + r)*SDIM + c] = core + 0.1f * d;
        }
    }
    if (has5) {
        float bo = bout[c5];
        if (c5 < 136) {
            int lm = c5 - 128;
            float cl = g_clm[lm];
            float m[8];
            #pragma unroll
            for (int mm = 0; mm < 8; mm++) m[mm] = g_Mlm[lm*8 + mm];
            #pragma unroll
            for (int rr = 0; rr < 8; rr++) {
                int r = rbase + rr;
                float d = cl - s_s[r*SSTRIDE + c5];
                #pragma unroll
                for (int mm = 0; mm < 8; mm++)
                    d += m[mm] * s_s[r*SSTRIDE + 128 + mm];
                out[(size_t)(row0 + r)*SDIM + c5] = acc5[rr] + bo + 0.1f * d;
            }
        } else {  // c5 == 136: movement channel, delta = 0
            #pragma unroll
            for (int rr = 0; rr < 8; rr++) {
                int r = rbase + rr;
                out[(size_t)(row0 + r)*SDIM + c5] = acc5[rr] + bo;
            }
        }
    }
}

extern "C" void kernel_launch(void* const* d_in, const int* in_sizes, int n_in,
                              void* d_out, int out_size) {
    const float* t        = (const float*)d_in[0];
    const float* state    = (const float*)d_in[1];
    const float* W0       = (const float*)d_in[2];
    const float* b0       = (const float*)d_in[3];
    const float* blkW1    = (const float*)d_in[4];
    const float* blkb1    = (const float*)d_in[5];
    const float* blkW2    = (const float*)d_in[6];
    const float* blkb2    = (const float*)d_in[7];
    const float* Wout     = (const float*)d_in[8];
    const float* bout     = (const float*)d_in[9];
    const float* lm_in_w  = (const float*)d_in[10];
    const float* lm_in_b  = (const float*)d_in[11];
    const float* lm_out_w = (const float*)d_in[12];
    const float* lm_out_b = (const float*)d_in[13];
    const float* ta_in_w  = (const float*)d_in[14];
    const float* ta_in_b  = (const float*)d_in[15];
    const float* ta_out_w = (const float*)d_in[16];
    const float* ta_out_b = (const float*)d_in[17];
    float* out = (float*)d_out;

    cudaFuncSetAttribute(ode_main, cudaFuncAttributeMaxDynamicSharedMemorySize, SMEM_BYTES);

    prep1<<<1, 256>>>(t, W0, b0, lm_in_w, lm_in_b, lm_out_w, lm_out_b,
                      ta_in_b, ta_out_w, ta_out_b);
    prep2<<<64, 256>>>(ta_in_w, ta_out_w);
    ode_main<<<BATCHN / ROWS, NTHREADS, SMEM_BYTES>>>(
        state, W0, blkW1, blkb1, blkW2, blkb2, Wout, bout, out);
}

// round 6
// speedup vs baseline: 6.9191x; 6.9191x over previous
#include <cuda_runtime.h>
#include <cuda_fp16.h>
#include <cstdint>

#define SD   137
#define HIDN 256
#define AP   264                      // act row stride in halves
#define OFF_H   0                     // s_h fp32 [128][256]  = 131072 B
#define OFF_ACT 131072                // act fp16 [128][264]  =  67584 B
#define OFF_B   (131072 + 67584)      // bufB fp16 [256][16]  =   8192 B
#define SMEM_SZ (OFF_B + 8192)

__device__ float g_b0p[HIDN];
__device__ float g_Waug[144*136];
__device__ float g_bias2[144];

__device__ __forceinline__ float tanh_fast(float x){
    float e = __expf(2.f*x); return 1.f - __fdividef(2.f, e + 1.f);
}

#define MMA(d, a, b0, b1) asm volatile( \
    "mma.sync.aligned.m16n8k16.row.col.f32.f16.f16.f32 " \
    "{%0,%1,%2,%3}, {%4,%5,%6,%7}, {%8,%9}, {%0,%1,%2,%3};" \
    : "+f"((d)[0]), "+f"((d)[1]), "+f"((d)[2]), "+f"((d)[3]) \
    : "r"((a)[0]), "r"((a)[1]), "r"((a)[2]), "r"((a)[3]), "r"(b0), "r"(b1))

// ---------------- prep ----------------
__global__ void prep1(const float* __restrict__ t, const float* __restrict__ W0,
                      const float* __restrict__ b0, const float* __restrict__ bout,
                      const float* __restrict__ lm_in_w, const float* __restrict__ lm_in_b,
                      const float* __restrict__ lm_out_w, const float* __restrict__ lm_out_b,
                      const float* __restrict__ ta_in_b,
                      const float* __restrict__ ta_out_w, const float* __restrict__ ta_out_b){
    int i = threadIdx.x;
    float ang = t[0] * (2.0f * 3.14159265358979323846f / 24.0f);
    g_b0p[i] = b0[i] + sinf(ang)*W0[i*139+137] + cosf(ang)*W0[i*139+138];
    if (i < 128) {
        float a = ta_out_b[i];
        for (int k = 0; k < 128; k++) a += ta_out_w[i*128+k] * ta_in_b[256+k];
        g_bias2[i] = bout[i] + 0.1f*a;
    } else if (i < 136) {
        int j = i - 128;
        float a = lm_out_b[j];
        for (int k = 0; k < 8; k++) a += lm_out_w[j*8+k] * lm_in_b[16+k];
        g_bias2[i] = bout[i] + 0.1f*a;
    } else if (i < 144) {
        g_bias2[i] = (i == 136) ? bout[136] : 0.f;
    }
}

__global__ void prepW(const float* __restrict__ ta_in_w, const float* __restrict__ ta_out_w,
                      const float* __restrict__ lm_in_w, const float* __restrict__ lm_out_w){
    int idx = blockIdx.x*blockDim.x + threadIdx.x;
    if (idx >= 144*136) return;
    int n = idx / 136, k = idx - n*136;
    float v = 0.f;
    if (n < 128 && k < 128) {
        for (int m = 0; m < 128; m++) v += ta_out_w[n*128+m] * ta_in_w[(256+m)*128+k];
    } else if (n >= 128 && n < 136 && k >= 128) {
        for (int m = 0; m < 8; m++) v += lm_out_w[(n-128)*8+m] * lm_in_w[(16+m)*8+(k-128)];
    }
    if (n == k && n < 136) v -= 1.f;
    g_Waug[idx] = 0.1f * v;
}

// ---------------- warp-mma GEMM: d += act(Mx K) @ W^T ----------------
__device__ __forceinline__ void gemm(const float* __restrict__ W, int ldw, int nvalid,
    int kmax, int nch, const __half* __restrict__ act, __half* __restrict__ bufB,
    float (*d)[8][4], int wm, int wn, int lane, int tid, int fresh)
{
    if (fresh)
        #pragma unroll
        for (int mi = 0; mi < 2; mi++)
            #pragma unroll
            for (int ni = 0; ni < 8; ni++)
                #pragma unroll
                for (int e = 0; e < 4; e++) d[mi][ni][e] = 0.f;

    const int r0 = lane >> 2, kk = (lane & 3) * 2;
    for (int ci = 0; ci < nch; ci++) {
        __syncthreads();                       // bufB free + act writes visible
        const int k0 = ci * 16;
        for (int i = tid; i < 4096; i += 512) {
            int n = i >> 4, kg = k0 + (i & 15);
            bufB[i] = __float2half_rn((n < nvalid && kg < kmax) ? W[n*ldw + kg] : 0.f);
        }
        __syncthreads();

        uint32_t a[2][4];
        #pragma unroll
        for (int mi = 0; mi < 2; mi++) {
            const __half* ap = act + (32*wm + 16*mi + r0)*AP + k0 + kk;
            a[mi][0] = *(const uint32_t*)ap;
            a[mi][1] = *(const uint32_t*)(ap + 8*AP);
            a[mi][2] = *(const uint32_t*)(ap + 8);
            a[mi][3] = *(const uint32_t*)(ap + 8*AP + 8);
        }
        #pragma unroll
        for (int ni = 0; ni < 8; ni++) {
            const __half* bp = bufB + (64*wn + 8*ni + r0)*16 + kk;
            uint32_t b0 = *(const uint32_t*)bp;
            uint32_t b1 = *(const uint32_t*)(bp + 8);
            MMA(d[0][ni], a[0], b0, b1);
            MMA(d[1][ni], a[1], b0, b1);
        }
    }
}

// mode: 0 relu->h+act, 1 tanh->act, 2 tanh(h+.)->h+act, 3 final store
__device__ __forceinline__ void epilogue(int mode, const float* __restrict__ bias,
    float (*d)[8][4], __half* __restrict__ act, float* __restrict__ s_h,
    float* __restrict__ outp, int wm, int wn, int lane)
{
    __syncthreads();                            // all mma done reading act
    const int r0 = lane >> 2, tg = lane & 3;
    #pragma unroll
    for (int mi = 0; mi < 2; mi++)
    #pragma unroll
    for (int ni = 0; ni < 8; ni++)
    #pragma unroll
    for (int e = 0; e < 4; e++) {
        int rr = 32*wm + 16*mi + r0 + (e >> 1)*8;
        int cc = 64*wn + 8*ni + tg*2 + (e & 1);
        float v = d[mi][ni][e];
        if (mode == 3) {
            if (cc < SD) outp[rr*SD + cc] = v + bias[cc];
        } else {
            float x = v + bias[cc];
            if (mode == 0)      x = fmaxf(x, 0.f);
            else if (mode == 1) x = tanh_fast(x);
            else                x = tanh_fast(s_h[rr*256 + cc] + x);
            if (mode != 1) s_h[rr*256 + cc] = x;
            act[rr*AP + cc] = __float2half_rn(x);
        }
    }
}

// ---------------- main ----------------
extern "C" __global__ void __launch_bounds__(512, 1)
ode_mma(const float* __restrict__ state,
        const float* __restrict__ W0,
        const float* __restrict__ blkW1, const float* __restrict__ blkb1,
        const float* __restrict__ blkW2, const float* __restrict__ blkb2,
        const float* __restrict__ Wout, float* __restrict__ out)
{
    extern __shared__ char smem[];
    float*  s_h  = (float*)(smem + OFF_H);
    __half* act  = (__half*)(smem + OFF_ACT);
    __half* bufB = (__half*)(smem + OFF_B);
    const int tid = threadIdx.x, lane = tid & 31, wid = tid >> 5;
    const int wm = wid & 3, wn = wid >> 2;
    const size_t row0 = (size_t)blockIdx.x * 128;
    const float* st = state + row0 * SD;

    // act := fp16(state), zero-padded to K=144
    for (int i = tid; i < 128*144; i += 512) {
        int r = i / 144, c = i - r*144;
        act[r*AP + c] = __float2half_rn(c < SD ? st[r*SD + c] : 0.f);
    }

    float d[2][8][4];

    // layer0: h = relu(state @ W0^T + b0p)
    gemm(W0, 139, 256, 137, 9, act, bufB, d, wm, wn, lane, tid, 1);
    epilogue(0, g_b0p, d, act, s_h, nullptr, wm, wn, lane);

    for (int b = 0; b < 4; b++) {
        gemm(blkW1 + b*65536, 256, 256, 256, 16, act, bufB, d, wm, wn, lane, tid, 1);
        epilogue(1, blkb1 + b*256, d, act, s_h, nullptr, wm, wn, lane);
        gemm(blkW2 + b*65536, 256, 256, 256, 16, act, bufB, d, wm, wn, lane, tid, 1);
        epilogue(2, blkb2 + b*256, d, act, s_h, nullptr, wm, wn, lane);
    }

    // core: d = h @ Wout^T
    gemm(Wout, 256, 137, 256, 16, act, bufB, d, wm, wn, lane, tid, 1);

    __syncthreads();                            // Wout mma done reading act
    for (int i = tid; i < 128*144; i += 512) {  // act := fp16(state) again
        int r = i / 144, c = i - r*144;
        act[r*AP + c] = __float2half_rn(c < SD ? st[r*SD + c] : 0.f);
    }

    // d += state @ Waug^T  (0.1*(delta ops - I), attentions folded)
    gemm(g_Waug, 136, 144, 136, 9, act, bufB, d, wm, wn, lane, tid, 0);

    epilogue(3, g_bias2, d, act, s_h, out + row0*SD, wm, wn, lane);
}

extern "C" void kernel_launch(void* const* d_in, const int* in_sizes, int n_in,
                              void* d_out, int out_size) {
    const float* t        = (const float*)d_in[0];
    const float* state    = (const float*)d_in[1];
    const float* W0       = (const float*)d_in[2];
    const float* b0       = (const float*)d_in[3];
    const float* blkW1    = (const float*)d_in[4];
    const float* blkb1    = (const float*)d_in[5];
    const float* blkW2    = (const float*)d_in[6];
    const float* blkb2    = (const float*)d_in[7];
    const float* Wout     = (const float*)d_in[8];
    const float* bout     = (const float*)d_in[9];
    const float* lm_in_w  = (const float*)d_in[10];
    const float* lm_in_b  = (const float*)d_in[11];
    const float* lm_out_w = (const float*)d_in[12];
    const float* lm_out_b = (const float*)d_in[13];
    const float* ta_in_w  = (const float*)d_in[14];
    const float* ta_in_b  = (const float*)d_in[15];
    const float* ta_out_w = (const float*)d_in[16];
    const float* ta_out_b = (const float*)d_in[17];
    float* out = (float*)d_out;

    cudaFuncSetAttribute(ode_mma, cudaFuncAttributeMaxDynamicSharedMemorySize, SMEM_SZ);
    prep1<<<1, 256>>>(t, W0, b0, bout, lm_in_w, lm_in_b, lm_out_w, lm_out_b,
                      ta_in_b, ta_out_w, ta_out_b);
    prepW<<<77, 256>>>(ta_in_w, ta_out_w, lm_in_w, lm_out_w);
    ode_mma<<<1024, 512, SMEM_SZ>>>(state, W0, blkW1, blkb1, blkW2, blkb2, Wout, out);
}

// round 7
// speedup vs baseline: 10.2524x; 1.4818x over previous
#include <cuda_runtime.h>
#include <cuda_fp16.h>
#include <cstdint>

#define SD   137
#define HIDN 256
#define AP   264
#define OFF_H   0                      // h fp32 [128][256] = 131072 B
#define OFF_ACT 131072                 // act fp16 [128][264] = 67584 B
#define OFF_B   (131072 + 67584)       // ring: 4 x 8192 B
#define SMEM_SZ (OFF_B + 4*8192)       // 231424

#define NCHUNK 162
__device__ float g_b0p[HIDN];
__device__ float g_Waug[144*136];
__device__ float g_bias2[144];
__device__ __align__(16) __half g_Wh[NCHUNK*4096];   // [chunk][n=256][k=16]

// chunk bases: W0=0(9), blk b: W1 @ 9+32b(16), W2 @ 9+32b+16(16), Wout=137(16), Waug=153(9)

__device__ __forceinline__ float tanh_fast(float x){
    float e = __expf(2.f*x); return 1.f - __fdividef(2.f, e + 1.f);
}
__device__ __forceinline__ uint32_t s2u(const void* p){
    uint32_t a;
    asm("{ .reg .u64 t; cvta.to.shared.u64 t, %1; cvt.u32.u64 %0, t; }" : "=r"(a) : "l"(p));
    return a;
}
#define MMA(d, a, b0, b1) asm volatile( \
    "mma.sync.aligned.m16n8k16.row.col.f32.f16.f16.f32 " \
    "{%0,%1,%2,%3}, {%4,%5,%6,%7}, {%8,%9}, {%0,%1,%2,%3};" \
    : "+f"((d)[0]), "+f"((d)[1]), "+f"((d)[2]), "+f"((d)[3]) \
    : "r"((a)[0]), "r"((a)[1]), "r"((a)[2]), "r"((a)[3]), "r"(b0), "r"(b1))
#define CP16(dst, src) asm volatile("cp.async.ca.shared.global [%0], [%1], 16;" :: "r"(dst), "l"(src))
#define CPC()  asm volatile("cp.async.commit_group;" ::: "memory")
#define CPW(n) asm volatile("cp.async.wait_group %0;" :: "n"(n) : "memory")

// ---------------- prep ----------------
__global__ void prep1(const float* __restrict__ t, const float* __restrict__ W0,
                      const float* __restrict__ b0, const float* __restrict__ bout,
                      const float* __restrict__ lm_in_w, const float* __restrict__ lm_in_b,
                      const float* __restrict__ lm_out_w, const float* __restrict__ lm_out_b,
                      const float* __restrict__ ta_in_b,
                      const float* __restrict__ ta_out_w, const float* __restrict__ ta_out_b){
    int i = threadIdx.x;
    float ang = t[0] * (2.0f * 3.14159265358979323846f / 24.0f);
    g_b0p[i] = b0[i] + sinf(ang)*W0[i*139+137] + cosf(ang)*W0[i*139+138];
    if (i < 128) {
        float a = ta_out_b[i];
        for (int k = 0; k < 128; k++) a += ta_out_w[i*128+k] * ta_in_b[256+k];
        g_bias2[i] = bout[i] + 0.1f*a;
    } else if (i < 136) {
        int j = i - 128;
        float a = lm_out_b[j];
        for (int k = 0; k < 8; k++) a += lm_out_w[j*8+k] * lm_in_b[16+k];
        g_bias2[i] = bout[i] + 0.1f*a;
    } else if (i < 144) {
        g_bias2[i] = (i == 136) ? bout[136] : 0.f;
    }
}

__global__ void prepW(const float* __restrict__ ta_in_w, const float* __restrict__ ta_out_w,
                      const float* __restrict__ lm_in_w, const float* __restrict__ lm_out_w){
    int idx = blockIdx.x*blockDim.x + threadIdx.x;
    if (idx >= 144*136) return;
    int n = idx / 136, k = idx - n*136;
    float v = 0.f;
    if (n < 128 && k < 128) {
        for (int m = 0; m < 128; m++) v += ta_out_w[n*128+m] * ta_in_w[(256+m)*128+k];
    } else if (n >= 128 && n < 136 && k >= 128) {
        for (int m = 0; m < 8; m++) v += lm_out_w[(n-128)*8+m] * lm_in_w[(16+m)*8+(k-128)];
    }
    if (n == k && n < 136) v -= 1.f;
    g_Waug[idx] = 0.1f * v;
}

__global__ void prepW2(const float* __restrict__ W0, const float* __restrict__ W1,
                       const float* __restrict__ W2, const float* __restrict__ Wout){
    int idx = blockIdx.x*blockDim.x + threadIdx.x;
    if (idx >= NCHUNK*4096) return;
    int c = idx >> 12, e = idx & 4095, n = e >> 4, kk = e & 15;
    const float* W; int ldw, nvalid, kmax, ci;
    if (c < 9)        { W = W0; ldw = 139; nvalid = 256; kmax = 137; ci = c; }
    else if (c < 137) { int cc = c - 9, b = cc >> 5, r = cc & 31;
                        W = (r < 16 ? W1 : W2) + b*65536; ci = r & 15;
                        ldw = 256; nvalid = 256; kmax = 256; }
    else if (c < 153) { W = Wout;   ldw = 256; nvalid = 137; kmax = 256; ci = c - 137; }
    else              { W = g_Waug; ldw = 136; nvalid = 144; kmax = 136; ci = c - 153; }
    int k = ci*16 + kk;
    g_Wh[idx] = __float2half_rn((n < nvalid && k < kmax) ? W[n*ldw + k] : 0.f);
}

// ---------------- pipelined GEMM: d += act @ Wchunks^T ----------------
__device__ __forceinline__ void gemm(const __half* __restrict__ Wc, int nch,
    const __half* __restrict__ act, const __half* __restrict__ bufB, uint32_t bufu,
    float (*d)[8][4], int wm, int wn, int lane, int tid, int fresh)
{
    if (fresh)
        #pragma unroll
        for (int mi = 0; mi < 2; mi++)
            #pragma unroll
            for (int ni = 0; ni < 8; ni++)
                #pragma unroll
                for (int e = 0; e < 4; e++) d[mi][ni][e] = 0.f;

    const int r0 = lane >> 2, kk2 = (lane & 3) * 2;
    const uint32_t dst0 = bufu + (uint32_t)tid*16;
    const __half* src0 = Wc + tid*8;

    CP16(dst0, src0); CPC();
    CP16(dst0 + 8192, src0 + 4096); CPC();

    for (int ci = 0; ci < nch; ci++) {
        if (ci + 2 < nch) {
            CP16(dst0 + (((ci+2)&3) << 13), src0 + (ci+2)*4096);
            CPC();
            CPW(2);
        } else {
            CPW(0);
        }
        __syncthreads();

        const __half* bs = bufB + ((ci & 3) << 12);
        const int k0 = ci * 16;
        uint32_t a[2][4];
        #pragma unroll
        for (int mi = 0; mi < 2; mi++) {
            const __half* ap = act + (32*wm + 16*mi + r0)*AP + k0 + kk2;
            a[mi][0] = *(const uint32_t*)ap;
            a[mi][1] = *(const uint32_t*)(ap + 8*AP);
            a[mi][2] = *(const uint32_t*)(ap + 8);
            a[mi][3] = *(const uint32_t*)(ap + 8*AP + 8);
        }
        #pragma unroll
        for (int ni = 0; ni < 8; ni++) {
            const __half* bp = bs + (64*wn + 8*ni + r0)*16 + kk2;
            uint32_t b0 = *(const uint32_t*)bp;
            uint32_t b1 = *(const uint32_t*)(bp + 8);
            MMA(d[0][ni], a[0], b0, b1);
            MMA(d[1][ni], a[1], b0, b1);
        }
    }
}

// mode: 0 relu->h+act, 1 tanh->act, 2 tanh(h+.)->h+act, 3 final store
__device__ __forceinline__ void epilogue(int mode, const float* __restrict__ bias,
    float (*d)[8][4], __half* __restrict__ act, float* __restrict__ s_h,
    float* __restrict__ outp, int wm, int wn, int lane)
{
    __syncthreads();
    const int r0 = lane >> 2, tg = lane & 3;
    #pragma unroll
    for (int mi = 0; mi < 2; mi++)
    #pragma unroll
    for (int ni = 0; ni < 8; ni++)
    #pragma unroll
    for (int e = 0; e < 4; e++) {
        int rr = 32*wm + 16*mi + r0 + (e >> 1)*8;
        int cc = 64*wn + 8*ni + tg*2 + (e & 1);
        float v = d[mi][ni][e];
        if (mode == 3) {
            if (cc < SD) outp[rr*SD + cc] = v + bias[cc];
        } else {
            float x = v + bias[cc];
            if (mode == 0)      x = fmaxf(x, 0.f);
            else if (mode == 1) x = tanh_fast(x);
            else                x = tanh_fast(s_h[rr*256 + cc] + x);
            if (mode != 1) s_h[rr*256 + cc] = x;
            act[rr*AP + cc] = __float2half_rn(x);
        }
    }
}

// ---------------- main ----------------
extern "C" __global__ void __launch_bounds__(512, 1)
ode_mma(const float* __restrict__ state, float* __restrict__ out)
{
    extern __shared__ char smem[];
    float*  s_h  = (float*)(smem + OFF_H);
    __half* act  = (__half*)(smem + OFF_ACT);
    __half* bufB = (__half*)(smem + OFF_B);
    const uint32_t bufu = s2u(bufB);
    const int tid = threadIdx.x, lane = tid & 31, wid = tid >> 5;
    const int wm = wid & 3, wn = wid >> 2;
    const size_t row0 = (size_t)blockIdx.x * 128;
    const float* st = state + row0 * SD;

    for (int i = tid; i < 128*144; i += 512) {
        int r = i / 144, c = i - r*144;
        act[r*AP + c] = __float2half_rn(c < SD ? st[r*SD + c] : 0.f);
    }

    float d[2][8][4];

    gemm(g_Wh,            9, act, bufB, bufu, d, wm, wn, lane, tid, 1);
    epilogue(0, g_b0p, d, act, s_h, nullptr, wm, wn, lane);

    for (int b = 0; b < 4; b++) {
        gemm(g_Wh + (size_t)(9 + 32*b)*4096,      16, act, bufB, bufu, d, wm, wn, lane, tid, 1);
        epilogue(1, nullptr, d, act, s_h, nullptr, wm, wn, lane);   // placeholder, see below
        gemm(g_Wh + (size_t)(9 + 32*b + 16)*4096, 16, act, bufB, bufu, d, wm, wn, lane, tid, 1);
        epilogue(2, nullptr, d, act, s_h, nullptr, wm, wn, lane);
    }

    gemm(g_Wh + (size_t)137*4096, 16, act, bufB, bufu, d, wm, wn, lane, tid, 1);

    __syncthreads();
    for (int i = tid; i < 128*144; i += 512) {
        int r = i / 144, c = i - r*144;
        act[r*AP + c] = __float2half_rn(c < SD ? st[r*SD + c] : 0.f);
    }

    gemm(g_Wh + (size_t)153*4096, 9, act, bufB, bufu, d, wm, wn, lane, tid, 0);
    epilogue(3, g_bias2, d, act, s_h, out + row0*SD, wm, wn, lane);
}

// wrapper that passes the real biases (kept out of ode_mma signature clutter)
extern "C" __global__ void __launch_bounds__(512, 1)
ode_mma_full(const float* __restrict__ state,
             const float* __restrict__ blkb1, const float* __restrict__ blkb2,
             float* __restrict__ out)
{
    extern __shared__ char smem[];
    float*  s_h  = (float*)(smem + OFF_H);
    __half* act  = (__half*)(smem + OFF_ACT);
    __half* bufB = (__half*)(smem + OFF_B);
    const uint32_t bufu = s2u(bufB);
    const int tid = threadIdx.x, lane = tid & 31, wid = tid >> 5;
    const int wm = wid & 3, wn = wid >> 2;
    const size_t row0 = (size_t)blockIdx.x * 128;
    const float* st = state + row0 * SD;

    for (int i = tid; i < 128*144; i += 512) {
        int r = i / 144, c = i - r*144;
        act[r*AP + c] = __float2half_rn(c < SD ? st[r*SD + c] : 0.f);
    }

    float d[2][8][4];

    gemm(g_Wh, 9, act, bufB, bufu, d, wm, wn, lane, tid, 1);
    epilogue(0, g_b0p, d, act, s_h, nullptr, wm, wn, lane);

    for (int b = 0; b < 4; b++) {
        gemm(g_Wh + (size_t)(9 + 32*b)*4096, 16, act, bufB, bufu, d, wm, wn, lane, tid, 1);
        epilogue(1, blkb1 + b*256, d, act, s_h, nullptr, wm, wn, lane);
        gemm(g_Wh + (size_t)(9 + 32*b + 16)*4096, 16, act, bufB, bufu, d, wm, wn, lane, tid, 1);
        epilogue(2, blkb2 + b*256, d, act, s_h, nullptr, wm, wn, lane);
    }

    gemm(g_Wh + (size_t)137*4096, 16, act, bufB, bufu, d, wm, wn, lane, tid, 1);

    __syncthreads();
    for (int i = tid; i < 128*144; i += 512) {
        int r = i / 144, c = i - r*144;
        act[r*AP + c] = __float2half_rn(c < SD ? st[r*SD + c] : 0.f);
    }

    gemm(g_Wh + (size_t)153*4096, 9, act, bufB, bufu, d, wm, wn, lane, tid, 0);
    epilogue(3, g_bias2, d, act, s_h, out + row0*SD, wm, wn, lane);
}

extern "C" void kernel_launch(void* const* d_in, const int* in_sizes, int n_in,
                              void* d_out, int out_size) {
    const float* t        = (const float*)d_in[0];
    const float* state    = (const float*)d_in[1];
    const float* W0       = (const float*)d_in[2];
    const float* b0       = (const float*)d_in[3];
    const float* blkW1    = (const float*)d_in[4];
    const float* blkb1    = (const float*)d_in[5];
    const float* blkW2    = (const float*)d_in[6];
    const float* blkb2    = (const float*)d_in[7];
    const float* Wout     = (const float*)d_in[8];
    const float* bout     = (const float*)d_in[9];
    const float* lm_in_w  = (const float*)d_in[10];
    const float* lm_in_b  = (const float*)d_in[11];
    const float* lm_out_w = (const float*)d_in[12];
    const float* lm_out_b = (const float*)d_in[13];
    const float* ta_in_w  = (const float*)d_in[14];
    const float* ta_in_b  = (const float*)d_in[15];
    const float* ta_out_w = (const float*)d_in[16];
    const float* ta_out_b = (const float*)d_in[17];
    float* out = (float*)d_out;

    cudaFuncSetAttribute(ode_mma_full, cudaFuncAttributeMaxDynamicSharedMemorySize, SMEM_SZ);
    prep1<<<1, 256>>>(t, W0, b0, bout, lm_in_w, lm_in_b, lm_out_w, lm_out_b,
                      ta_in_b, ta_out_w, ta_out_b);
    prepW<<<77, 256>>>(ta_in_w, ta_out_w, lm_in_w, lm_out_w);
    prepW2<<<2592, 256>>>(W0, blkW1, blkW2, Wout);
    ode_mma_full<<<1024, 512, SMEM_SZ>>>(state, blkb1, blkb2, out);
}

// round 8
// speedup vs baseline: 13.6302x; 1.3295x over previous
#include <cuda_runtime.h>
#include <cuda_fp16.h>
#include <cstdint>

#define SD   137
#define HIDN 256
#define AP   264
#define OFF_H   0                      // h fp32 [128][256] = 131072 B
#define OFF_ACT 131072                 // act fp16 [128][264] = 67584 B
#define OFF_B   (131072 + 67584)       // ring: 4 x 8192 B
#define SMEM_SZ (OFF_B + 4*8192)       // 231424

#define NCHUNK 162
__device__ float g_b0p[HIDN];
__device__ float g_Waug[144*136];
__device__ float g_bias2[144];
__device__ __align__(16) __half g_Wh[NCHUNK*4096];   // [chunk][swizzled 256x16]

__device__ __forceinline__ float tanh_fast(float x){
    float e = __expf(2.f*x); return 1.f - __fdividef(2.f, e + 1.f);
}
__device__ __forceinline__ uint32_t s2u(const void* p){
    uint32_t a;
    asm("{ .reg .u64 t; cvta.to.shared.u64 t, %1; cvt.u32.u64 %0, t; }" : "=r"(a) : "l"(p));
    return a;
}
#define MMA(d, a0, a1, a2, a3, b0, b1) asm volatile( \
    "mma.sync.aligned.m16n8k16.row.col.f32.f16.f16.f32 " \
    "{%0,%1,%2,%3}, {%4,%5,%6,%7}, {%8,%9}, {%0,%1,%2,%3};" \
    : "+f"((d)[0]), "+f"((d)[1]), "+f"((d)[2]), "+f"((d)[3]) \
    : "r"(a0), "r"(a1), "r"(a2), "r"(a3), "r"(b0), "r"(b1))
#define LDM4(r, addr) asm volatile( \
    "ldmatrix.sync.aligned.m8n8.x4.shared.b16 {%0,%1,%2,%3}, [%4];" \
    : "=r"((r)[0]), "=r"((r)[1]), "=r"((r)[2]), "=r"((r)[3]) : "r"(addr))
#define CP16(dst, src) asm volatile("cp.async.ca.shared.global [%0], [%1], 16;" :: "r"(dst), "l"(src))
#define CPC()  asm volatile("cp.async.commit_group;" ::: "memory")
#define CPW(n) asm volatile("cp.async.wait_group %0;" :: "n"(n) : "memory")

// ---------------- prep ----------------
__global__ void prep1(const float* __restrict__ t, const float* __restrict__ W0,
                      const float* __restrict__ b0, const float* __restrict__ bout,
                      const float* __restrict__ lm_in_w, const float* __restrict__ lm_in_b,
                      const float* __restrict__ lm_out_w, const float* __restrict__ lm_out_b,
                      const float* __restrict__ ta_in_b,
                      const float* __restrict__ ta_out_w, const float* __restrict__ ta_out_b){
    int i = threadIdx.x;
    float ang = t[0] * (2.0f * 3.14159265358979323846f / 24.0f);
    g_b0p[i] = b0[i] + sinf(ang)*W0[i*139+137] + cosf(ang)*W0[i*139+138];
    if (i < 128) {
        float a = ta_out_b[i];
        for (int k = 0; k < 128; k++) a += ta_out_w[i*128+k] * ta_in_b[256+k];
        g_bias2[i] = bout[i] + 0.1f*a;
    } else if (i < 136) {
        int j = i - 128;
        float a = lm_out_b[j];
        for (int k = 0; k < 8; k++) a += lm_out_w[j*8+k] * lm_in_b[16+k];
        g_bias2[i] = bout[i] + 0.1f*a;
    } else if (i < 144) {
        g_bias2[i] = (i == 136) ? bout[136] : 0.f;
    }
}

__global__ void prepW(const float* __restrict__ ta_in_w, const float* __restrict__ ta_out_w,
                      const float* __restrict__ lm_in_w, const float* __restrict__ lm_out_w){
    int idx = blockIdx.x*blockDim.x + threadIdx.x;
    if (idx >= 144*136) return;
    int n = idx / 136, k = idx - n*136;
    float v = 0.f;
    if (n < 128 && k < 128) {
        for (int m = 0; m < 128; m++) v += ta_out_w[n*128+m] * ta_in_w[(256+m)*128+k];
    } else if (n >= 128 && n < 136 && k >= 128) {
        for (int m = 0; m < 8; m++) v += lm_out_w[(n-128)*8+m] * lm_in_w[(16+m)*8+(k-128)];
    }
    if (n == k && n < 136) v -= 1.f;
    g_Waug[idx] = 0.1f * v;
}

// weights -> fp16, chunked [256 x 16], B-rows swizzled for conflict-free ldmatrix:
// 16B unit of (n, khalf) stored at unit u = 2n + (khalf ^ ((n>>2)&1))
__global__ void prepW2(const float* __restrict__ W0, const float* __restrict__ W1,
                       const float* __restrict__ W2, const float* __restrict__ Wout){
    int idx = blockIdx.x*blockDim.x + threadIdx.x;
    if (idx >= NCHUNK*4096) return;
    int c = idx >> 12, e = idx & 4095, n = e >> 4, kk = e & 15;
    const float* W; int ldw, nvalid, kmax, ci;
    if (c < 9)        { W = W0; ldw = 139; nvalid = 256; kmax = 137; ci = c; }
    else if (c < 137) { int cc = c - 9, b = cc >> 5, r = cc & 31;
                        W = (r < 16 ? W1 : W2) + b*65536; ci = r & 15;
                        ldw = 256; nvalid = 256; kmax = 256; }
    else if (c < 153) { W = Wout;   ldw = 256; nvalid = 137; kmax = 256; ci = c - 137; }
    else              { W = g_Waug; ldw = 136; nvalid = 144; kmax = 136; ci = c - 153; }
    int k = ci*16 + kk;
    float v = (n < nvalid && k < kmax) ? W[n*ldw + k] : 0.f;
    int u = n*2 + (((kk>>3) ^ (n>>2)) & 1);
    g_Wh[(size_t)c*4096 + u*8 + (kk & 7)] = __float2half_rn(v);
}

// ---------------- pipelined GEMM: d += act @ Wchunks^T ----------------
__device__ __forceinline__ void gemm(const __half* __restrict__ Wc, int nch,
    uint32_t actu, uint32_t bufu, const uint32_t* boff, uint32_t arow0, uint32_t arow1,
    float (*d)[8][4], int tid, int fresh)
{
    if (fresh)
        #pragma unroll
        for (int mi = 0; mi < 2; mi++)
            #pragma unroll
            for (int ni = 0; ni < 8; ni++)
                #pragma unroll
                for (int e = 0; e < 4; e++) d[mi][ni][e] = 0.f;

    const uint32_t dst0 = bufu + (uint32_t)tid*16;
    const __half* src0 = Wc + tid*8;

    CP16(dst0, src0); CPC();
    CP16(dst0 + 8192, src0 + 4096); CPC();

    for (int ci = 0; ci < nch; ci++) {
        if (ci + 2 < nch) {
            CP16(dst0 + (((ci+2)&3) << 13), src0 + (ci+2)*4096);
            CPC();
            CPW(2);
        } else {
            CPW(0);
        }
        __syncthreads();

        const uint32_t bs = bufu + ((ci & 3) << 13);
        const uint32_t k2 = (uint32_t)(ci * 32);   // k0*2 bytes
        uint32_t a0[4], a1[4];
        LDM4(a0, actu + arow0 + k2);
        LDM4(a1, actu + arow1 + k2);
        #pragma unroll
        for (int p = 0; p < 4; p++) {
            uint32_t b[4];
            LDM4(b, bs + boff[p]);
            MMA(d[0][2*p],   a0[0], a0[1], a0[2], a0[3], b[0], b[1]);
            MMA(d[1][2*p],   a1[0], a1[1], a1[2], a1[3], b[0], b[1]);
            MMA(d[0][2*p+1], a0[0], a0[1], a0[2], a0[3], b[2], b[3]);
            MMA(d[1][2*p+1], a1[0], a1[1], a1[2], a1[3], b[2], b[3]);
        }
    }
}

// mode: 0 relu->h+act, 1 tanh->act, 2 tanh(h+.)->h+act, 3 final store
__device__ __forceinline__ void epilogue(int mode, const float* __restrict__ bias,
    float (*d)[8][4], __half* __restrict__ act, float* __restrict__ s_h,
    float* __restrict__ outp, int wm, int wn, int lane)
{
    __syncthreads();
    const int r0 = lane >> 2, tg = lane & 3;
    #pragma unroll
    for (int mi = 0; mi < 2; mi++)
    #pragma unroll
    for (int ni = 0; ni < 8; ni++)
    #pragma unroll
    for (int e = 0; e < 4; e++) {
        int rr = 32*wm + 16*mi + r0 + (e >> 1)*8;
        int cc = 64*wn + 8*ni + tg*2 + (e & 1);
        float v = d[mi][ni][e];
        if (mode == 3) {
            if (cc < SD) outp[rr*SD + cc] = v + bias[cc];
        } else {
            float x = v + bias[cc];
            if (mode == 0)      x = fmaxf(x, 0.f);
            else if (mode == 1) x = tanh_fast(x);
            else                x = tanh_fast(s_h[rr*256 + cc] + x);
            if (mode != 1) s_h[rr*256 + cc] = x;
            act[rr*AP + cc] = __float2half_rn(x);
        }
    }
}

// ---------------- main ----------------
extern "C" __global__ void __launch_bounds__(512, 1)
ode_mma_full(const float* __restrict__ state,
             const float* __restrict__ blkb1, const float* __restrict__ blkb2,
             float* __restrict__ out)
{
    extern __shared__ char smem[];
    float*  s_h  = (float*)(smem + OFF_H);
    __half* act  = (__half*)(smem + OFF_ACT);
    __half* bufB = (__half*)(smem + OFF_B);
    const uint32_t bufu = s2u(bufB);
    const uint32_t actu = s2u(act);
    const int tid = threadIdx.x, lane = tid & 31, wid = tid >> 5;
    const int wm = wid & 3, wn = wid >> 2;
    const size_t row0 = (size_t)blockIdx.x * 128;
    const float* st = state + row0 * SD;

    // ldmatrix A row offsets (bytes): lanes 0-7 rows 0-7 k0-7, 8-15 rows 8-15 k0-7,
    // 16-23 rows 0-7 k8-15, 24-31 rows 8-15 k8-15
    const uint32_t arow0 = (uint32_t)(((32*wm + (lane & 15))*AP + ((lane >> 4) << 3)) * 2);
    const uint32_t arow1 = arow0 + (uint32_t)(16*AP*2);
    // ldmatrix B offsets per ni-pair (chunk-invariant, swizzled layout)
    uint32_t boff[4];
    {
        int nn = 64*wn + (lane & 7) + ((lane >> 4) << 3);
        int kh = (lane >> 3) & 1;
        #pragma unroll
        for (int p = 0; p < 4; p++) {
            int n = nn + 16*p;
            boff[p] = (uint32_t)((n*2 + ((kh ^ (n >> 2)) & 1)) * 16);
        }
    }

    for (int i = tid; i < 128*144; i += 512) {
        int r = i / 144, c = i - r*144;
        act[r*AP + c] = __float2half_rn(c < SD ? st[r*SD + c] : 0.f);
    }

    float d[2][8][4];

    gemm(g_Wh, 9, actu, bufu, boff, arow0, arow1, d, tid, 1);
    epilogue(0, g_b0p, d, act, s_h, nullptr, wm, wn, lane);

    for (int b = 0; b < 4; b++) {
        gemm(g_Wh + (size_t)(9 + 32*b)*4096, 16, actu, bufu, boff, arow0, arow1, d, tid, 1);
        epilogue(1, blkb1 + b*256, d, act, s_h, nullptr, wm, wn, lane);
        gemm(g_Wh + (size_t)(9 + 32*b + 16)*4096, 16, actu, bufu, boff, arow0, arow1, d, tid, 1);
        epilogue(2, blkb2 + b*256, d, act, s_h, nullptr, wm, wn, lane);
    }

    gemm(g_Wh + (size_t)137*4096, 16, actu, bufu, boff, arow0, arow1, d, tid, 1);

    __syncthreads();
    for (int i = tid; i < 128*144; i += 512) {
        int r = i / 144, c = i - r*144;
        act[r*AP + c] = __float2half_rn(c < SD ? st[r*SD + c] : 0.f);
    }

    gemm(g_Wh + (size_t)153*4096, 9, actu, bufu, boff, arow0, arow1, d, tid, 0);
    epilogue(3, g_bias2, d, act, s_h, out + row0*SD, wm, wn, lane);
}

extern "C" void kernel_launch(void* const* d_in, const int* in_sizes, int n_in,
                              void* d_out, int out_size) {
    const float* t        = (const float*)d_in[0];
    const float* state    = (const float*)d_in[1];
    const float* W0       = (const float*)d_in[2];
    const float* b0       = (const float*)d_in[3];
    const float* blkW1    = (const float*)d_in[4];
    const float* blkb1    = (const float*)d_in[5];
    const float* blkW2    = (const float*)d_in[6];
    const float* blkb2    = (const float*)d_in[7];
    const float* Wout     = (const float*)d_in[8];
    const float* bout     = (const float*)d_in[9];
    const float* lm_in_w  = (const float*)d_in[10];
    const float* lm_in_b  = (const float*)d_in[11];
    const float* lm_out_w = (const float*)d_in[12];
    const float* lm_out_b = (const float*)d_in[13];
    const float* ta_in_w  = (const float*)d_in[14];
    const float* ta_in_b  = (const float*)d_in[15];
    const float* ta_out_w = (const float*)d_in[16];
    const float* ta_out_b = (const float*)d_in[17];
    float* out = (float*)d_out;

    cudaFuncSetAttribute(ode_mma_full, cudaFuncAttributeMaxDynamicSharedMemorySize, SMEM_SZ);
    prep1<<<1, 256>>>(t, W0, b0, bout, lm_in_w, lm_in_b, lm_out_w, lm_out_b,
                      ta_in_b, ta_out_w, ta_out_b);
    prepW<<<77, 256>>>(ta_in_w, ta_out_w, lm_in_w, lm_out_w);
    prepW2<<<2592, 256>>>(W0, blkW1, blkW2, Wout);
    ode_mma_full<<<1024, 512, SMEM_SZ>>>(state, blkb1, blkb2, out);
}